// round 2
// baseline (speedup 1.0000x reference)
#include <cuda_runtime.h>
#include <math.h>

#define IC 256
typedef unsigned long long u64;
typedef unsigned int u32;

// ---------------- device scratch (no allocations allowed) ----------------
__device__ __align__(256) float g_xs[4 * IC * 128 * 128];   // share-tower output
__device__ __align__(256) float g_px[4 * 1024 * IC];        // pat tower on 32x32 region, pixel-major
__device__ __align__(256) float g_part[2][4 * 128 * 128];   // ent ehead partial dots (per 128-ch half)
__device__ __align__(256) float g_wT[3][IC * 9 * IC];       // weights [ci][tap][n]
__device__ __align__(256) float g_scale[3][3][IC];          // fused BN scale [tower][lvl][ch]
__device__ __align__(256) float g_bias[3][3][IC];           // fused BN bias (conv bias folded)
__device__ int g_sel[4][512];

// ---------------- f32x2 helpers ----------------
__device__ __forceinline__ u64 pack2(float v) {
    u64 d; unsigned r = __float_as_uint(v);
    asm("mov.b64 %0, {%1, %2};" : "=l"(d) : "r"(r), "r"(r));
    return d;
}
__device__ __forceinline__ u64 ffma2(u64 a, u64 b, u64 c) {
    u64 d; asm("fma.rn.f32x2 %0, %1, %2, %3;" : "=l"(d) : "l"(a), "l"(b), "l"(c));
    return d;
}
__device__ __forceinline__ void unpack2(u64 v, float& lo, float& hi) {
    unsigned a, b; asm("mov.b64 {%0, %1}, %2;" : "=r"(a), "=r"(b) : "l"(v));
    lo = __uint_as_float(a); hi = __uint_as_float(b);
}
__device__ __forceinline__ float sigm(float x) { return 1.f / (1.f + expf(-x)); }

// ---------------- prep: weight transpose + BN fold ----------------
struct PrepArgs { const float *w[3], *b[3], *g[3], *bb[3], *m[3], *v[3]; };

__global__ void prep_k(PrepArgs P) {
    int idx = blockIdx.x * blockDim.x + threadIdx.x;
    if (idx < 9 * IC) {
        int t = idx / (3 * IC), rem = idx % (3 * IC), l = rem / IC, ch = rem % IC;
        float s = P.g[t][l * IC + ch] / sqrtf(P.v[t][l * IC + ch] + 1e-5f);
        g_scale[t][l][ch] = s;
        g_bias[t][l][ch] = P.bb[t][l * IC + ch] + (P.b[t][ch] - P.m[t][l * IC + ch]) * s;
    }
    int j = idx - 9 * IC;
    if (j >= 0 && j < 3 * IC * 9 * IC) {
        int t = j / (IC * 9 * IC), rem = j % (IC * 9 * IC);
        int ci = rem / (9 * IC), tap = (rem / IC) % 9, n = rem % IC;
        g_wT[t][ci * 9 * IC + tap * IC + n] = P.w[t][n * IC * 9 + ci * 9 + tap];
    }
}

// ---------------- conv3x3 + BN + ReLU ----------------
// Tile: 8 rows x 16 cols x 128 out-ch (blockIdx.z half). 256 threads.
// Thread: cg=tid>>4 -> 8 out-ch (4 f32x2 pairs); sg=tid&15 -> (row=sg>>1, 8 cols at (sg&1)*8).
// MODE 0: store to g_xs. MODE 1: ent -> partial ehead dot into g_part. MODE 2: pat -> g_px (32x32).
template<int MODE>
__global__ __launch_bounds__(256)
void conv3x3_k(const float* __restrict__ inp, int H, int W, int tower, int lvl,
               const float* __restrict__ ehw, int tilesX)
{
    __shared__ __align__(16) float sIn[1520];   // 8ci x 10 x 19 (stride 19)
    __shared__ __align__(16) float sW[9216];    // 8ci x 9tap x 128n

    const int tid = threadIdx.x;
    const int b = blockIdx.y, nblk = blockIdx.z;
    const int tx = blockIdx.x % tilesX, ty = blockIdx.x / tilesX;
    const int y0 = ty * 8, x0 = tx * 16;
    const int cg = tid >> 4, sg = tid & 15;
    const int srow = sg >> 1, sx = (sg & 1) * 8;

    const float* __restrict__ src = (MODE == 0) ? inp : g_xs;
    const float* __restrict__ wT = g_wT[tower];

    u64 acc[4][8];
#pragma unroll
    for (int i = 0; i < 4; i++)
#pragma unroll
        for (int j = 0; j < 8; j++) acc[i][j] = 0ull;

    for (int c0 = 0; c0 < IC; c0 += 8) {
        for (int e = tid; e < 1520; e += 256) {
            int ci = e / 190, rem = e % 190;
            int r = rem / 19, cc = rem % 19;
            int gy = y0 - 1 + r, gx = x0 - 1 + cc;
            float v = 0.f;
            if (cc < 18 && gy >= 0 && gy < H && gx >= 0 && gx < W)
                v = src[(((size_t)b * IC + c0 + ci) * H + gy) * W + gx];
            sIn[e] = v;
        }
        for (int e4 = tid; e4 < 2304; e4 += 256) {
            int ci = e4 / 288, rem = e4 % 288;
            int tap = rem / 32, n4 = rem % 32;
            float4 v = *(const float4*)(wT + (size_t)(c0 + ci) * (9 * IC) + tap * IC + nblk * 128 + n4 * 4);
            *(float4*)(sW + ci * 1152 + tap * 128 + n4 * 4) = v;
        }
        __syncthreads();

#pragma unroll 1
        for (int ci = 0; ci < 8; ci++) {
#pragma unroll
            for (int dy = 0; dy < 3; dy++) {
                const float* rp = sIn + ci * 190 + (srow + dy) * 19 + sx;
                u64 rr[10];
#pragma unroll
                for (int j = 0; j < 10; j++) rr[j] = pack2(rp[j]);
                const u64* wp = (const u64*)(sW + ci * 1152 + dy * 384 + cg * 8);
#pragma unroll
                for (int dx = 0; dx < 3; dx++) {
                    u64 w0 = wp[dx * 64 + 0], w1 = wp[dx * 64 + 1];
                    u64 w2 = wp[dx * 64 + 2], w3 = wp[dx * 64 + 3];
#pragma unroll
                    for (int m = 0; m < 8; m++) {
                        acc[0][m] = ffma2(w0, rr[m + dx], acc[0][m]);
                        acc[1][m] = ffma2(w1, rr[m + dx], acc[1][m]);
                        acc[2][m] = ffma2(w2, rr[m + dx], acc[2][m]);
                        acc[3][m] = ffma2(w3, rr[m + dx], acc[3][m]);
                    }
                }
            }
        }
        __syncthreads();
    }

    const float* sc = g_scale[tower][lvl];
    const float* bi = g_bias[tower][lvl];
    float psum[8];
#pragma unroll
    for (int m = 0; m < 8; m++) psum[m] = 0.f;
    const int y = y0 + srow, xb = x0 + sx;

#pragma unroll
    for (int n2 = 0; n2 < 4; n2++) {
        int cha = nblk * 128 + cg * 8 + 2 * n2, chb = cha + 1;
        float sa = sc[cha], ta = bi[cha], sb = sc[chb], tb = bi[chb];
        float va[8], vb[8];
#pragma unroll
        for (int m = 0; m < 8; m++) {
            float lo, hi; unpack2(acc[n2][m], lo, hi);
            va[m] = fmaxf(fmaf(lo, sa, ta), 0.f);
            vb[m] = fmaxf(fmaf(hi, sb, tb), 0.f);
        }
        if (MODE == 0) {
            float* oa = g_xs + (((size_t)b * IC + cha) * H + y) * W + xb;
            float* ob = g_xs + (((size_t)b * IC + chb) * H + y) * W + xb;
            *(float4*)(oa)     = make_float4(va[0], va[1], va[2], va[3]);
            *(float4*)(oa + 4) = make_float4(va[4], va[5], va[6], va[7]);
            *(float4*)(ob)     = make_float4(vb[0], vb[1], vb[2], vb[3]);
            *(float4*)(ob + 4) = make_float4(vb[4], vb[5], vb[6], vb[7]);
        } else if (MODE == 1) {
            float wa = ehw[cha], wb = ehw[chb];
#pragma unroll
            for (int m = 0; m < 8; m++) psum[m] += va[m] * wa + vb[m] * wb;
        } else {
#pragma unroll
            for (int m = 0; m < 8; m++) {
                float* o = g_px + ((size_t)(b * 1024 + y * 32 + xb + m)) * IC;
                o[cha] = va[m]; o[chb] = vb[m];
            }
        }
    }

    if (MODE == 1) {
        float* s_red = sW;  // reuse
#pragma unroll
        for (int m = 0; m < 8; m++) s_red[cg * 128 + srow * 16 + sx + m] = psum[m];
        __syncthreads();
        if (tid < 128) {
            float s = 0.f;
#pragma unroll
            for (int c2 = 0; c2 < 16; c2++) s += s_red[c2 * 128 + tid];
            int yy = y0 + (tid >> 4), xx = x0 + (tid & 15);
            g_part[nblk][b * H * W + yy * W + xx] = s;
        }
    }
}

// ---------------- em: combine halves + sigmoid ----------------
__global__ void em_k(int HW, const float* __restrict__ ehb, float* __restrict__ out_em) {
    int i = blockIdx.x * blockDim.x + threadIdx.x;
    if (i < 4 * HW)
        out_em[i] = sigm(g_part[0][i] + g_part[1][i] + ehb[0]);
}

// ---------------- top-k: full bitonic sort of 1024 (desc, stable) ----------------
__global__ void sort_k(const int* __restrict__ coords, const float* __restrict__ em,
                       int H, int W, int nk, float* __restrict__ out_xy) {
    __shared__ u64 sk[1024];
    int b = blockIdx.x, t = threadIdx.x;
    for (int p = t; p < 1024; p += 512) {
        int r = coords[p], c = coords[1024 + p];
        float v = em[b * H * W + r * W + c];
        u64 key = ((u64)__float_as_uint(v) << 32) | (u32)(1023 - p);
        sk[p] = ~key;  // ascending sort of ~key == descending of key
    }
    __syncthreads();
    for (int k = 2; k <= 1024; k <<= 1)
        for (int j = k >> 1; j > 0; j >>= 1) {
            for (int i2 = t; i2 < 1024; i2 += 512) {
                int l = i2 ^ j;
                if (l > i2) {
                    u64 a = sk[i2], bb = sk[l];
                    bool up = ((i2 & k) == 0);
                    if ((a > bb) == up) { sk[i2] = bb; sk[l] = a; }
                }
            }
            __syncthreads();
        }
    if (t < nk) {
        u64 key = ~sk[t];
        int p = 1023 - (int)(key & 0xFFFFFFFFu);
        g_sel[b][t] = p;
        int r = coords[p], c = coords[1024 + p];
        out_xy[(b * nk + t) * 2]     = (float)r;
        out_xy[(b * nk + t) * 2 + 1] = (float)c;
    }
}

// ---------------- head: 4 dots of 256 + sigmoid + box ----------------
__global__ void head_k(const int* __restrict__ coords, const float* __restrict__ hw,
                       const float* __restrict__ hb, int nk, float* __restrict__ out_fin) {
    int b = blockIdx.y;
    int k = blockIdx.x * 4 + (threadIdx.x >> 5);
    int lane = threadIdx.x & 31;
    if (k >= nk) return;
    int p = g_sel[b][k];
    int r = coords[p], c = coords[1024 + p];
    const float* af = g_px + ((size_t)(b * 1024 + r * 32 + c)) * IC;
    float acc[4] = {0.f, 0.f, 0.f, 0.f};
#pragma unroll
    for (int q = 0; q < 2; q++) {
        int ch = lane * 8 + q * 4;
        float4 a4 = *(const float4*)(af + ch);
#pragma unroll
        for (int j = 0; j < 4; j++) {
            float4 w4 = *(const float4*)(hw + j * IC + ch);
            acc[j] += a4.x * w4.x + a4.y * w4.y + a4.z * w4.z + a4.w * w4.w;
        }
    }
#pragma unroll
    for (int o = 16; o; o >>= 1)
#pragma unroll
        for (int j = 0; j < 4; j++) acc[j] += __shfl_down_sync(0xffffffffu, acc[j], o);
    if (lane == 0) {
        float pc0 = sigm(acc[0] + hb[0]), pc1 = sigm(acc[1] + hb[1]);
        float pc2 = sigm(acc[2] + hb[2]), pc3 = sigm(acc[3] + hb[3]);
        *(float4*)(out_fin + (size_t)(b * nk + k) * 4) =
            make_float4((float)r - 16.f * pc0, (float)c - 16.f * pc1,
                        (float)r + 16.f * pc2, (float)c + 16.f * pc3);
    }
}

// ---------------- launch ----------------
extern "C" void kernel_launch(void* const* d_in, const int* in_sizes, int n_in,
                              void* d_out, int out_size) {
    const float* feats[3] = {(const float*)d_in[0], (const float*)d_in[1], (const float*)d_in[2]};
    const int* coords = (const int*)d_in[3];
    const float* ehw = (const float*)d_in[22];
    const float* ehb = (const float*)d_in[23];
    const float* hw  = (const float*)d_in[24];
    const float* hb  = (const float*)d_in[25];
    float* out = (float*)d_out;

    PrepArgs P;
    for (int t = 0; t < 3; t++) {
        int base = 4 + 6 * t;
        P.w[t]  = (const float*)d_in[base + 0];
        P.b[t]  = (const float*)d_in[base + 1];
        P.g[t]  = (const float*)d_in[base + 2];
        P.bb[t] = (const float*)d_in[base + 3];
        P.m[t]  = (const float*)d_in[base + 4];
        P.v[t]  = (const float*)d_in[base + 5];
    }
    int prepN = 9 * IC + 3 * IC * 9 * IC;
    prep_k<<<(prepN + 255) / 256, 256>>>(P);

    const int Hs[3] = {128, 64, 32};
    const int NKs[3] = {512, 256, 128};
    const int emOff[3]  = {0,     77824, 100352};
    const int finOff[3] = {65536, 94208, 104448};
    const int xyOff[3]  = {73728, 98304, 106496};

    for (int lvl = 0; lvl < 3; lvl++) {
        int H = Hs[lvl], W = H, HW = H * W, nk = NKs[lvl];
        int tX = W / 16, tiles = tX * (H / 8);
        conv3x3_k<0><<<dim3(tiles, 4, 2), 256>>>(feats[lvl], H, W, 0, lvl, nullptr, tX);
        conv3x3_k<1><<<dim3(tiles, 4, 2), 256>>>(nullptr, H, W, 1, lvl, ehw, tX);
        conv3x3_k<2><<<dim3(8, 4, 2), 256>>>(nullptr, H, W, 2, lvl, nullptr, 2);
        em_k<<<(4 * HW + 255) / 256, 256>>>(HW, ehb, out + emOff[lvl]);
        sort_k<<<4, 512>>>(coords, out + emOff[lvl], H, W, nk, out + xyOff[lvl]);
        head_k<<<dim3(nk / 4, 4), 128>>>(coords, hw, hb, nk, out + finOff[lvl]);
    }
}

// round 3
// speedup vs baseline: 1.2768x; 1.2768x over previous
#include <cuda_runtime.h>
#include <math.h>

#define IC 256
typedef unsigned long long u64;
typedef unsigned int u32;

// ---------------- device scratch ----------------
// per-level xs offsets (floats): lvl0 4*256*16384, lvl1 4*256*4096, lvl2 4*256*1024
__device__ __align__(256) float g_xs[22020096];          // 88MB: all 3 levels
__device__ __align__(256) float g_px[3 * 1048576];       // pat output per level, pixel-major
__device__ __align__(256) float g_part[2][86016];        // ent ehead partials per half, all levels
__device__ __align__(256) float g_wT[3][IC * 9 * IC];
__device__ __align__(256) float g_scale[3][3][IC];
__device__ __align__(256) float g_bias[3][3][IC];
__device__ int g_sel[3][4][512];

__device__ __forceinline__ u64 pack2(float v) {
    u64 d; unsigned r = __float_as_uint(v);
    asm("mov.b64 %0, {%1, %2};" : "=l"(d) : "r"(r), "r"(r));
    return d;
}
__device__ __forceinline__ u64 ffma2(u64 a, u64 b, u64 c) {
    u64 d; asm("fma.rn.f32x2 %0, %1, %2, %3;" : "=l"(d) : "l"(a), "l"(b), "l"(c));
    return d;
}
__device__ __forceinline__ void unpack2(u64 v, float& lo, float& hi) {
    unsigned a, b; asm("mov.b64 {%0, %1}, %2;" : "=r"(a), "=r"(b) : "l"(v));
    lo = __uint_as_float(a); hi = __uint_as_float(b);
}
__device__ __forceinline__ float sigm(float x) { return 1.f / (1.f + expf(-x)); }

// ---------------- prep ----------------
struct PrepArgs { const float *w[3], *b[3], *g[3], *bb[3], *m[3], *v[3]; };

__global__ void prep_k(PrepArgs P) {
    int idx = blockIdx.x * blockDim.x + threadIdx.x;
    if (idx < 9 * IC) {
        int t = idx / (3 * IC), rem = idx % (3 * IC), l = rem / IC, ch = rem % IC;
        float s = P.g[t][l * IC + ch] / sqrtf(P.v[t][l * IC + ch] + 1e-5f);
        g_scale[t][l][ch] = s;
        g_bias[t][l][ch] = P.bb[t][l * IC + ch] + (P.b[t][ch] - P.m[t][l * IC + ch]) * s;
    }
    int j = idx - 9 * IC;
    if (j >= 0 && j < 3 * IC * 9 * IC) {
        int t = j / (IC * 9 * IC), rem = j % (IC * 9 * IC);
        int ci = rem / (9 * IC), tap = (rem / IC) % 9, n = rem % IC;
        g_wT[t][ci * 9 * IC + tap * IC + n] = P.w[t][n * IC * 9 + ci * 9 + tap];
    }
}

// ---------------- fused multi-segment conv3x3 + BN + ReLU ----------------
// mode==tower: 0 share (gmem feats -> g_xs), 1 ent (g_xs -> g_part dot), 2 pat (g_xs -> g_px 32x32)
struct FusedArgs {
    int segEnd[3];
    int mode[3], lvl[3], H[3], tilesX[3];
    const float* fsrc[3];
};

__global__ __launch_bounds__(256, 2)
void convF_k(FusedArgs A) {
    __shared__ __align__(16) float sIn[1520];   // 8ci x 10 x 19
    __shared__ __align__(16) float sW[9216];    // 8ci x 9tap x 128n

    const int tid = threadIdx.x;
    const int b = blockIdx.y, nblk = blockIdx.z;
    const int bx = blockIdx.x;
    const int s = (bx >= A.segEnd[0]) + (bx >= A.segEnd[1]);
    const int tile = bx - (s ? A.segEnd[s - 1] : 0);
    const int mode = A.mode[s], lvl = A.lvl[s];
    const int H = A.H[s], W = H, tX = A.tilesX[s];

    const size_t xsoff = (lvl == 0) ? 0ul : ((lvl == 1) ? 16777216ul : 20971520ul);
    const int partoff = (lvl == 0) ? 0 : ((lvl == 1) ? 65536 : 81920);

    const int tx = tile % tX, ty = tile / tX;
    const int y0 = ty * 8, x0 = tx * 16;
    const int cg = tid >> 4, sg = tid & 15;
    const int srow = sg >> 1, sx = (sg & 1) * 8;

    const float* __restrict__ src = (mode == 0) ? A.fsrc[s] : (g_xs + xsoff);
    const float* __restrict__ wT = g_wT[mode];

    u64 acc[4][8];
#pragma unroll
    for (int i = 0; i < 4; i++)
#pragma unroll
        for (int j = 0; j < 8; j++) acc[i][j] = 0ull;

    for (int c0 = 0; c0 < IC; c0 += 8) {
        for (int e = tid; e < 1520; e += 256) {
            int ci = e / 190, rem = e % 190;
            int r = rem / 19, cc = rem % 19;
            int gy = y0 - 1 + r, gx = x0 - 1 + cc;
            float v = 0.f;
            if (cc < 18 && gy >= 0 && gy < H && gx >= 0 && gx < W)
                v = src[(((size_t)b * IC + c0 + ci) * H + gy) * W + gx];
            sIn[e] = v;
        }
        for (int e4 = tid; e4 < 2304; e4 += 256) {
            int ci = e4 / 288, rem = e4 % 288;
            int tap = rem / 32, n4 = rem % 32;
            float4 v = *(const float4*)(wT + (size_t)(c0 + ci) * (9 * IC) + tap * IC + nblk * 128 + n4 * 4);
            *(float4*)(sW + ci * 1152 + tap * 128 + n4 * 4) = v;
        }
        __syncthreads();

#pragma unroll 1
        for (int ci = 0; ci < 8; ci++) {
#pragma unroll
            for (int dy = 0; dy < 3; dy++) {
                const float* rp = sIn + ci * 190 + (srow + dy) * 19 + sx;
                u64 rr[10];
#pragma unroll
                for (int j = 0; j < 10; j++) rr[j] = pack2(rp[j]);
                const u64* wp = (const u64*)(sW + ci * 1152 + dy * 384 + cg * 8);
#pragma unroll
                for (int dx = 0; dx < 3; dx++) {
                    u64 w0 = wp[dx * 64 + 0], w1 = wp[dx * 64 + 1];
                    u64 w2 = wp[dx * 64 + 2], w3 = wp[dx * 64 + 3];
#pragma unroll
                    for (int m = 0; m < 8; m++) {
                        acc[0][m] = ffma2(w0, rr[m + dx], acc[0][m]);
                        acc[1][m] = ffma2(w1, rr[m + dx], acc[1][m]);
                        acc[2][m] = ffma2(w2, rr[m + dx], acc[2][m]);
                        acc[3][m] = ffma2(w3, rr[m + dx], acc[3][m]);
                    }
                }
            }
        }
        __syncthreads();
    }

    const float* sc = g_scale[mode][lvl];
    const float* bi = g_bias[mode][lvl];
    float psum[8];
#pragma unroll
    for (int m = 0; m < 8; m++) psum[m] = 0.f;
    const int y = y0 + srow, xb = x0 + sx;

#pragma unroll
    for (int n2 = 0; n2 < 4; n2++) {
        int cha = nblk * 128 + cg * 8 + 2 * n2, chb = cha + 1;
        float sa = sc[cha], ta = bi[cha], sb = sc[chb], tb = bi[chb];
        float va[8], vb[8];
#pragma unroll
        for (int m = 0; m < 8; m++) {
            float lo, hi; unpack2(acc[n2][m], lo, hi);
            va[m] = fmaxf(fmaf(lo, sa, ta), 0.f);
            vb[m] = fmaxf(fmaf(hi, sb, tb), 0.f);
        }
        if (mode == 0) {
            float* oa = g_xs + xsoff + (((size_t)b * IC + cha) * H + y) * W + xb;
            float* ob = g_xs + xsoff + (((size_t)b * IC + chb) * H + y) * W + xb;
            *(float4*)(oa)     = make_float4(va[0], va[1], va[2], va[3]);
            *(float4*)(oa + 4) = make_float4(va[4], va[5], va[6], va[7]);
            *(float4*)(ob)     = make_float4(vb[0], vb[1], vb[2], vb[3]);
            *(float4*)(ob + 4) = make_float4(vb[4], vb[5], vb[6], vb[7]);
        } else if (mode == 1) {
            float wa = A.fsrc[s][cha], wb = A.fsrc[s][chb];  // ehead weight passed via fsrc
#pragma unroll
            for (int m = 0; m < 8; m++) psum[m] += va[m] * wa + vb[m] * wb;
        } else {
#pragma unroll
            for (int m = 0; m < 8; m++) {
                float* o = g_px + (size_t)lvl * 1048576 + (size_t)(b * 1024 + y * 32 + xb + m) * IC;
                o[cha] = va[m]; o[chb] = vb[m];
            }
        }
    }

    if (mode == 1) {
        float* s_red = sW;
#pragma unroll
        for (int m = 0; m < 8; m++) s_red[cg * 128 + srow * 16 + sx + m] = psum[m];
        __syncthreads();
        if (tid < 128) {
            float acc2 = 0.f;
#pragma unroll
            for (int c2 = 0; c2 < 16; c2++) acc2 += s_red[c2 * 128 + tid];
            int yy = y0 + (tid >> 4), xx = x0 + (tid & 15);
            g_part[nblk][partoff + b * H * W + yy * W + xx] = acc2;
        }
    }
}

// ---------------- em for all levels ----------------
__global__ void em_k(const float* __restrict__ ehb, float* __restrict__ out) {
    int i = blockIdx.x * blockDim.x + threadIdx.x;
    if (i >= 86016) return;
    int emo = (i < 65536) ? 0 : ((i < 81920) ? 77824 - 65536 : 100352 - 81920);
    out[emo + i] = sigm(g_part[0][i] + g_part[1][i] + ehb[0]);
}

// ---------------- sort (all levels): stable descending top-k via bitonic 1024 ----------------
__global__ void sort_k(const int* __restrict__ coords, const float* __restrict__ out_em_base,
                       float* __restrict__ out) {
    __shared__ u64 sk[1024];
    int lvl = blockIdx.x, b = blockIdx.y, t = threadIdx.x;
    int H = (lvl == 0) ? 128 : ((lvl == 1) ? 64 : 32);
    int nk = (lvl == 0) ? 512 : ((lvl == 1) ? 256 : 128);
    int emOff = (lvl == 0) ? 0 : ((lvl == 1) ? 77824 : 100352);
    int xyOff = (lvl == 0) ? 73728 : ((lvl == 1) ? 98304 : 106496);
    const float* em = out_em_base + emOff + b * H * H;

    for (int p = t; p < 1024; p += 512) {
        int r = coords[p], c = coords[1024 + p];
        float v = em[r * H + c];
        u64 key = ((u64)__float_as_uint(v) << 32) | (u32)(1023 - p);
        sk[p] = ~key;
    }
    __syncthreads();
    for (int k = 2; k <= 1024; k <<= 1)
        for (int j = k >> 1; j > 0; j >>= 1) {
            for (int i2 = t; i2 < 1024; i2 += 512) {
                int l = i2 ^ j;
                if (l > i2) {
                    u64 a = sk[i2], bb = sk[l];
                    bool up = ((i2 & k) == 0);
                    if ((a > bb) == up) { sk[i2] = bb; sk[l] = a; }
                }
            }
            __syncthreads();
        }
    if (t < nk) {
        u64 key = ~sk[t];
        int p = 1023 - (int)(key & 0xFFFFFFFFu);
        g_sel[lvl][b][t] = p;
        int r = coords[p], c = coords[1024 + p];
        out[xyOff + (b * nk + t) * 2]     = (float)r;
        out[xyOff + (b * nk + t) * 2 + 1] = (float)c;
    }
}

// ---------------- head (all levels) ----------------
__global__ void head_k(const int* __restrict__ coords, const float* __restrict__ hw,
                       const float* __restrict__ hb, float* __restrict__ out) {
    int lvl = blockIdx.z, b = blockIdx.y;
    int nk = (lvl == 0) ? 512 : ((lvl == 1) ? 256 : 128);
    int finOff = (lvl == 0) ? 65536 : ((lvl == 1) ? 94208 : 104448);
    int k = blockIdx.x * 4 + (threadIdx.x >> 5);
    int lane = threadIdx.x & 31;
    if (k >= nk) return;
    int p = g_sel[lvl][b][k];
    int r = coords[p], c = coords[1024 + p];
    const float* af = g_px + (size_t)lvl * 1048576 + (size_t)(b * 1024 + r * 32 + c) * IC;
    float acc[4] = {0.f, 0.f, 0.f, 0.f};
#pragma unroll
    for (int q = 0; q < 2; q++) {
        int ch = lane * 8 + q * 4;
        float4 a4 = *(const float4*)(af + ch);
#pragma unroll
        for (int j = 0; j < 4; j++) {
            float4 w4 = *(const float4*)(hw + j * IC + ch);
            acc[j] += a4.x * w4.x + a4.y * w4.y + a4.z * w4.z + a4.w * w4.w;
        }
    }
#pragma unroll
    for (int o = 16; o; o >>= 1)
#pragma unroll
        for (int j = 0; j < 4; j++) acc[j] += __shfl_down_sync(0xffffffffu, acc[j], o);
    if (lane == 0) {
        float pc0 = sigm(acc[0] + hb[0]), pc1 = sigm(acc[1] + hb[1]);
        float pc2 = sigm(acc[2] + hb[2]), pc3 = sigm(acc[3] + hb[3]);
        *(float4*)(out + finOff + (size_t)(b * nk + k) * 4) =
            make_float4((float)r - 16.f * pc0, (float)c - 16.f * pc1,
                        (float)r + 16.f * pc2, (float)c + 16.f * pc3);
    }
}

// ---------------- launch ----------------
extern "C" void kernel_launch(void* const* d_in, const int* in_sizes, int n_in,
                              void* d_out, int out_size) {
    const float* feat0 = (const float*)d_in[0];
    const float* feat1 = (const float*)d_in[1];
    const float* feat2 = (const float*)d_in[2];
    const int* coords = (const int*)d_in[3];
    const float* ehw = (const float*)d_in[22];
    const float* ehb = (const float*)d_in[23];
    const float* hw  = (const float*)d_in[24];
    const float* hb  = (const float*)d_in[25];
    float* out = (float*)d_out;

    PrepArgs P;
    for (int t = 0; t < 3; t++) {
        int base = 4 + 6 * t;
        P.w[t]  = (const float*)d_in[base + 0];
        P.b[t]  = (const float*)d_in[base + 1];
        P.g[t]  = (const float*)d_in[base + 2];
        P.bb[t] = (const float*)d_in[base + 3];
        P.m[t]  = (const float*)d_in[base + 4];
        P.v[t]  = (const float*)d_in[base + 5];
    }
    int prepN = 9 * IC + 3 * IC * 9 * IC;
    prep_k<<<(prepN + 255) / 256, 256>>>(P);

    // F1: share l0 (128 tiles)
    {
        FusedArgs A = {{128, 128, 128}, {0, 0, 0}, {0, 0, 0}, {128, 128, 128}, {8, 8, 8},
                       {feat0, feat0, feat0}};
        convF_k<<<dim3(128, 4, 2), 256>>>(A);
    }
    // F2: ent l0 (128) + pat l0 (8) + share l1 (32)
    {
        FusedArgs A = {{128, 136, 168}, {1, 2, 0}, {0, 0, 1}, {128, 128, 64}, {8, 2, 4},
                       {ehw, nullptr, feat1}};
        convF_k<<<dim3(168, 4, 2), 256>>>(A);
    }
    // F3: ent l1 (32) + pat l1 (8) + share l2 (8)
    {
        FusedArgs A = {{32, 40, 48}, {1, 2, 0}, {1, 1, 2}, {64, 64, 32}, {4, 2, 2},
                       {ehw, nullptr, feat2}};
        convF_k<<<dim3(48, 4, 2), 256>>>(A);
    }
    // F4: ent l2 (8) + pat l2 (8)
    {
        FusedArgs A = {{8, 16, 16}, {1, 2, 2}, {2, 2, 2}, {32, 32, 32}, {2, 2, 2},
                       {ehw, nullptr, nullptr}};
        convF_k<<<dim3(16, 4, 2), 256>>>(A);
    }

    em_k<<<(86016 + 255) / 256, 256>>>(ehb, out);
    sort_k<<<dim3(3, 4), 512>>>(coords, out, out);
    head_k<<<dim3(128, 4, 3), 128>>>(coords, hw, hb, out);
}

// round 4
// speedup vs baseline: 1.4125x; 1.1063x over previous
#include <cuda_runtime.h>
#include <math.h>

#define IC 256
typedef unsigned long long u64;
typedef unsigned int u32;

// ---------------- device scratch ----------------
__device__ __align__(256) float g_xs[22020096];          // xs all levels: off 0 / 16777216 / 20971520
__device__ __align__(256) float g_px[3 * 1048576];       // pat output per level, pixel-major
__device__ __align__(256) float g_part[2][86016];        // ent ehead partials per half
__device__ __align__(256) float g_wT[3][IC * 9 * IC];
__device__ __align__(256) float g_scale[3][3][IC];
__device__ __align__(256) float g_bias[3][3][IC];
__device__ int g_sel[3][4][512];
__device__ int g_cnt[3];                                 // share-level completion counters

// segment table: share0,share1,share2, ent0,pat0, ent1,pat1, ent2,pat2
__constant__ int c_segStart[10] = {0, 1024, 1280, 1344, 2368, 2432, 2688, 2752, 2816, 2880};
__constant__ int c_mode[9] = {0, 0, 0, 1, 2, 1, 2, 1, 2};
__constant__ int c_lvl[9]  = {0, 1, 2, 0, 0, 1, 1, 2, 2};
__constant__ int c_H[9]    = {128, 64, 32, 128, 128, 64, 64, 32, 32};
__constant__ int c_tX[9]   = {8, 4, 2, 8, 2, 4, 2, 2, 2};
__constant__ int c_need[3] = {1024, 256, 64};

__device__ __forceinline__ u64 pack2(float v) {
    u64 d; unsigned r = __float_as_uint(v);
    asm("mov.b64 %0, {%1, %2};" : "=l"(d) : "r"(r), "r"(r));
    return d;
}
__device__ __forceinline__ u64 ffma2(u64 a, u64 b, u64 c) {
    u64 d; asm("fma.rn.f32x2 %0, %1, %2, %3;" : "=l"(d) : "l"(a), "l"(b), "l"(c));
    return d;
}
__device__ __forceinline__ void unpack2(u64 v, float& lo, float& hi) {
    unsigned a, b; asm("mov.b64 {%0, %1}, %2;" : "=r"(a), "=r"(b) : "l"(v));
    lo = __uint_as_float(a); hi = __uint_as_float(b);
}
__device__ __forceinline__ float sigm(float x) { return 1.f / (1.f + expf(-x)); }

// ---------------- prep: BN fold + weight transpose + counter reset ----------------
struct PrepArgs { const float *w[3], *b[3], *g[3], *bb[3], *m[3], *v[3]; };

__global__ void prep_k(PrepArgs P) {
    int idx = blockIdx.x * blockDim.x + threadIdx.x;
    if (idx < 3) g_cnt[idx] = 0;
    if (idx < 9 * IC) {
        int t = idx / (3 * IC), rem = idx % (3 * IC), l = rem / IC, ch = rem % IC;
        float s = P.g[t][l * IC + ch] / sqrtf(P.v[t][l * IC + ch] + 1e-5f);
        g_scale[t][l][ch] = s;
        g_bias[t][l][ch] = P.bb[t][l * IC + ch] + (P.b[t][ch] - P.m[t][l * IC + ch]) * s;
    }
    int j = idx - 9 * IC;
    if (j >= 0 && j < 3 * IC * 9 * IC) {
        int t = j / (IC * 9 * IC), rem = j % (IC * 9 * IC);
        int ci = rem / (9 * IC), tap = (rem / IC) % 9, n = rem % IC;
        g_wT[t][ci * 9 * IC + tap * IC + n] = P.w[t][n * IC * 9 + ci * 9 + tap];
    }
}

// ---------------- mega conv kernel: all towers, all levels, one launch ----------------
__global__ __launch_bounds__(256, 2)
void convM_k(const float* __restrict__ f0, const float* __restrict__ f1,
             const float* __restrict__ f2, const float* __restrict__ ehw) {
    __shared__ __align__(16) float sIn[1520];   // 8ci x 10 x 19
    __shared__ __align__(16) float sW[9216];    // 8ci x 9tap x 128n

    const int tid = threadIdx.x;
    const int bid = blockIdx.x;
    int s = 0;
    while (bid >= c_segStart[s + 1]) s++;
    const int mode = c_mode[s], lvl = c_lvl[s];
    const int H = c_H[s], W = H, tX = c_tX[s];
    const int i = bid - c_segStart[s];
    const int tile = i >> 3, b = (i >> 1) & 3, nblk = i & 1;

    // dependency gate: ent/pat wait for their level's share tower
    if (mode != 0) {
        if (tid == 0) {
            int need = c_need[lvl];
            long long guard = 0;
            while (atomicAdd(&g_cnt[lvl], 0) < need && guard < 5000000LL) {
                __nanosleep(100); guard++;
            }
        }
        __syncthreads();
        __threadfence();
    }

    const size_t xsoff = (lvl == 0) ? 0ul : ((lvl == 1) ? 16777216ul : 20971520ul);
    const int partoff = (lvl == 0) ? 0 : ((lvl == 1) ? 65536 : 81920);

    const int tx = tile % tX, ty = tile / tX;
    const int y0 = ty * 8, x0 = tx * 16;
    const int cg = tid >> 4, sg = tid & 15;
    const int srow = sg >> 1, sx = (sg & 1) * 8;

    const float* __restrict__ src =
        (mode != 0) ? (g_xs + xsoff) : ((lvl == 0) ? f0 : ((lvl == 1) ? f1 : f2));
    const float* __restrict__ wT = g_wT[mode];

    u64 acc[4][8];
#pragma unroll
    for (int ii = 0; ii < 4; ii++)
#pragma unroll
        for (int j = 0; j < 8; j++) acc[ii][j] = 0ull;

    for (int c0 = 0; c0 < IC; c0 += 8) {
        for (int e = tid; e < 1520; e += 256) {
            int ci = e / 190, rem = e % 190;
            int r = rem / 19, cc = rem % 19;
            int gy = y0 - 1 + r, gx = x0 - 1 + cc;
            float v = 0.f;
            if (cc < 18 && gy >= 0 && gy < H && gx >= 0 && gx < W)
                v = src[(((size_t)b * IC + c0 + ci) * H + gy) * W + gx];
            sIn[e] = v;
        }
        for (int e4 = tid; e4 < 2304; e4 += 256) {
            int ci = e4 / 288, rem = e4 % 288;
            int tap = rem / 32, n4 = rem % 32;
            float4 v = *(const float4*)(wT + (size_t)(c0 + ci) * (9 * IC) + tap * IC + nblk * 128 + n4 * 4);
            *(float4*)(sW + ci * 1152 + tap * 128 + n4 * 4) = v;
        }
        __syncthreads();

#pragma unroll 1
        for (int ci = 0; ci < 8; ci++) {
#pragma unroll
            for (int dy = 0; dy < 3; dy++) {
                const float* rp = sIn + ci * 190 + (srow + dy) * 19 + sx;
                u64 rr[10];
#pragma unroll
                for (int j = 0; j < 10; j++) rr[j] = pack2(rp[j]);
                const u64* wp = (const u64*)(sW + ci * 1152 + dy * 384 + cg * 8);
#pragma unroll
                for (int dx = 0; dx < 3; dx++) {
                    u64 w0 = wp[dx * 64 + 0], w1 = wp[dx * 64 + 1];
                    u64 w2 = wp[dx * 64 + 2], w3 = wp[dx * 64 + 3];
#pragma unroll
                    for (int m = 0; m < 8; m++) {
                        acc[0][m] = ffma2(w0, rr[m + dx], acc[0][m]);
                        acc[1][m] = ffma2(w1, rr[m + dx], acc[1][m]);
                        acc[2][m] = ffma2(w2, rr[m + dx], acc[2][m]);
                        acc[3][m] = ffma2(w3, rr[m + dx], acc[3][m]);
                    }
                }
            }
        }
        __syncthreads();
    }

    const float* sc = g_scale[mode][lvl];
    const float* bi = g_bias[mode][lvl];
    float psum[8];
#pragma unroll
    for (int m = 0; m < 8; m++) psum[m] = 0.f;
    const int y = y0 + srow, xb = x0 + sx;

#pragma unroll
    for (int n2 = 0; n2 < 4; n2++) {
        int cha = nblk * 128 + cg * 8 + 2 * n2, chb = cha + 1;
        float sa = sc[cha], ta = bi[cha], sb = sc[chb], tb = bi[chb];
        float va[8], vb[8];
#pragma unroll
        for (int m = 0; m < 8; m++) {
            float lo, hi; unpack2(acc[n2][m], lo, hi);
            va[m] = fmaxf(fmaf(lo, sa, ta), 0.f);
            vb[m] = fmaxf(fmaf(hi, sb, tb), 0.f);
        }
        if (mode == 0) {
            float* oa = g_xs + xsoff + (((size_t)b * IC + cha) * H + y) * W + xb;
            float* ob = g_xs + xsoff + (((size_t)b * IC + chb) * H + y) * W + xb;
            *(float4*)(oa)     = make_float4(va[0], va[1], va[2], va[3]);
            *(float4*)(oa + 4) = make_float4(va[4], va[5], va[6], va[7]);
            *(float4*)(ob)     = make_float4(vb[0], vb[1], vb[2], vb[3]);
            *(float4*)(ob + 4) = make_float4(vb[4], vb[5], vb[6], vb[7]);
        } else if (mode == 1) {
            float wa = ehw[cha], wb = ehw[chb];
#pragma unroll
            for (int m = 0; m < 8; m++) psum[m] += va[m] * wa + vb[m] * wb;
        } else {
#pragma unroll
            for (int m = 0; m < 8; m++) {
                float* o = g_px + (size_t)lvl * 1048576 + (size_t)(b * 1024 + y * 32 + xb + m) * IC;
                o[cha] = va[m]; o[chb] = vb[m];
            }
        }
    }

    if (mode == 1) {
        float* s_red = sW;
#pragma unroll
        for (int m = 0; m < 8; m++) s_red[cg * 128 + srow * 16 + sx + m] = psum[m];
        __syncthreads();
        if (tid < 128) {
            float acc2 = 0.f;
#pragma unroll
            for (int c2 = 0; c2 < 16; c2++) acc2 += s_red[c2 * 128 + tid];
            int yy = y0 + (tid >> 4), xx = x0 + (tid & 15);
            g_part[nblk][partoff + b * H * W + yy * W + xx] = acc2;
        }
    } else if (mode == 0) {
        // signal completion of this share block
        __threadfence();
        __syncthreads();
        if (tid == 0) atomicAdd(&g_cnt[lvl], 1);
    }
}

// ---------------- em for all levels ----------------
__global__ void em_k(const float* __restrict__ ehb, float* __restrict__ out) {
    int i = blockIdx.x * blockDim.x + threadIdx.x;
    if (i >= 86016) return;
    int emo = (i < 65536) ? 0 : ((i < 81920) ? 77824 - 65536 : 100352 - 81920);
    out[emo + i] = sigm(g_part[0][i] + g_part[1][i] + ehb[0]);
}

// ---------------- sort: stable descending top-k via bitonic 1024 ----------------
__global__ void sort_k(const int* __restrict__ coords, const float* __restrict__ base,
                       float* __restrict__ out) {
    __shared__ u64 sk[1024];
    int lvl = blockIdx.x, b = blockIdx.y, t = threadIdx.x;
    int H = (lvl == 0) ? 128 : ((lvl == 1) ? 64 : 32);
    int nk = (lvl == 0) ? 512 : ((lvl == 1) ? 256 : 128);
    int emOff = (lvl == 0) ? 0 : ((lvl == 1) ? 77824 : 100352);
    int xyOff = (lvl == 0) ? 73728 : ((lvl == 1) ? 98304 : 106496);
    const float* em = base + emOff + b * H * H;

    for (int p = t; p < 1024; p += 512) {
        int r = coords[p], c = coords[1024 + p];
        float v = em[r * H + c];
        u64 key = ((u64)__float_as_uint(v) << 32) | (u32)(1023 - p);
        sk[p] = ~key;
    }
    __syncthreads();
    for (int k = 2; k <= 1024; k <<= 1)
        for (int j = k >> 1; j > 0; j >>= 1) {
            for (int i2 = t; i2 < 1024; i2 += 512) {
                int l = i2 ^ j;
                if (l > i2) {
                    u64 a = sk[i2], bb = sk[l];
                    bool up = ((i2 & k) == 0);
                    if ((a > bb) == up) { sk[i2] = bb; sk[l] = a; }
                }
            }
            __syncthreads();
        }
    if (t < nk) {
        u64 key = ~sk[t];
        int p = 1023 - (int)(key & 0xFFFFFFFFu);
        g_sel[lvl][b][t] = p;
        int r = coords[p], c = coords[1024 + p];
        out[xyOff + (b * nk + t) * 2]     = (float)r;
        out[xyOff + (b * nk + t) * 2 + 1] = (float)c;
    }
}

// ---------------- head ----------------
__global__ void head_k(const int* __restrict__ coords, const float* __restrict__ hw,
                       const float* __restrict__ hb, float* __restrict__ out) {
    int lvl = blockIdx.z, b = blockIdx.y;
    int nk = (lvl == 0) ? 512 : ((lvl == 1) ? 256 : 128);
    int finOff = (lvl == 0) ? 65536 : ((lvl == 1) ? 94208 : 104448);
    int k = blockIdx.x * 4 + (threadIdx.x >> 5);
    int lane = threadIdx.x & 31;
    if (k >= nk) return;
    int p = g_sel[lvl][b][k];
    int r = coords[p], c = coords[1024 + p];
    const float* af = g_px + (size_t)lvl * 1048576 + (size_t)(b * 1024 + r * 32 + c) * IC;
    float acc[4] = {0.f, 0.f, 0.f, 0.f};
#pragma unroll
    for (int q = 0; q < 2; q++) {
        int ch = lane * 8 + q * 4;
        float4 a4 = *(const float4*)(af + ch);
#pragma unroll
        for (int j = 0; j < 4; j++) {
            float4 w4 = *(const float4*)(hw + j * IC + ch);
            acc[j] += a4.x * w4.x + a4.y * w4.y + a4.z * w4.z + a4.w * w4.w;
        }
    }
#pragma unroll
    for (int o = 16; o; o >>= 1)
#pragma unroll
        for (int j = 0; j < 4; j++) acc[j] += __shfl_down_sync(0xffffffffu, acc[j], o);
    if (lane == 0) {
        float pc0 = sigm(acc[0] + hb[0]), pc1 = sigm(acc[1] + hb[1]);
        float pc2 = sigm(acc[2] + hb[2]), pc3 = sigm(acc[3] + hb[3]);
        *(float4*)(out + finOff + (size_t)(b * nk + k) * 4) =
            make_float4((float)r - 16.f * pc0, (float)c - 16.f * pc1,
                        (float)r + 16.f * pc2, (float)c + 16.f * pc3);
    }
}

// ---------------- launch ----------------
extern "C" void kernel_launch(void* const* d_in, const int* in_sizes, int n_in,
                              void* d_out, int out_size) {
    const float* feat0 = (const float*)d_in[0];
    const float* feat1 = (const float*)d_in[1];
    const float* feat2 = (const float*)d_in[2];
    const int* coords = (const int*)d_in[3];
    const float* ehw = (const float*)d_in[22];
    const float* ehb = (const float*)d_in[23];
    const float* hw  = (const float*)d_in[24];
    const float* hb  = (const float*)d_in[25];
    float* out = (float*)d_out;

    PrepArgs P;
    for (int t = 0; t < 3; t++) {
        int base = 4 + 6 * t;
        P.w[t]  = (const float*)d_in[base + 0];
        P.b[t]  = (const float*)d_in[base + 1];
        P.g[t]  = (const float*)d_in[base + 2];
        P.bb[t] = (const float*)d_in[base + 3];
        P.m[t]  = (const float*)d_in[base + 4];
        P.v[t]  = (const float*)d_in[base + 5];
    }
    int prepN = 9 * IC + 3 * IC * 9 * IC;
    prep_k<<<(prepN + 255) / 256, 256>>>(P);

    convM_k<<<2880, 256>>>(feat0, feat1, feat2, ehw);

    em_k<<<(86016 + 255) / 256, 256>>>(ehb, out);
    sort_k<<<dim3(3, 4), 512>>>(coords, out, out);
    head_k<<<dim3(128, 4, 3), 128>>>(coords, hw, hb, out);
}